// round 8
// baseline (speedup 1.0000x reference)
#include <cuda_runtime.h>

// RWKV WKV recurrence, B=16, T=2048, D=1024 fp32.
// 4 time-chunks of 512 (affine-state scan split) for occupancy, plus
// float2-vectorized channels: each LDG.64 carries 2x the bytes per
// scoreboard slot (per-warp MLP_eff is capped ~16 slots; bytes-in-flight
// is the binding resource for this HBM-streaming kernel).
//
// Kernel A: chunk 0 exact (writes out + state@512); chunks 1,2 summarized
//           as (P, A, B) from zero init  [a_end = P*a_in + A].
// Kernel B: chunks 1..3 exact, carry composed from summaries.

#define TT   2048
#define DD2  512            // D in float2 units
#define NCH2 8192           // B * D / 2 channel-pairs
#define LCH  512            // chunk length (timesteps)
#define UU   8              // timesteps per inner block (double buffer)
#define NB   (LCH / UU)     // 64 inner blocks

// scratch: [a512 | b512 | P1 | A1 | B1 | P2 | A2 | B2], each NCH2 float2
__device__ float2 g_scr[8 * NCH2];

template<int DO_OUT>
__device__ __forceinline__ void run_chunk(const float2* __restrict__ kp,
                                          const float2* __restrict__ vp,
                                          const float2* __restrict__ wp,
                                          float2* __restrict__ op,
                                          float2& a, float2& b, float2& p)
{
    float2 kb[2][UU], vb[2][UU], wb[2][UU];

#pragma unroll
    for (int i = 0; i < UU; i++) {
        kb[0][i] = __ldcs(kp + i * DD2);
        vb[0][i] = __ldcs(vp + i * DD2);
        wb[0][i] = __ldcs(wp + i * DD2);
    }

    int cur = 0;
    for (int blk = 0; blk < NB - 1; blk++) {
        const int nxt = cur ^ 1;
        const float2* kq = kp + (blk + 1) * UU * DD2;
        const float2* vq = vp + (blk + 1) * UU * DD2;
        const float2* wq = wp + (blk + 1) * UU * DD2;
#pragma unroll
        for (int i = 0; i < UU; i++) {
            kb[nxt][i] = __ldcs(kq + i * DD2);
            vb[nxt][i] = __ldcs(vq + i * DD2);
            wb[nxt][i] = __ldcs(wq + i * DD2);
        }
        float2* o = op + blk * UU * DD2;
#pragma unroll
        for (int i = 0; i < UU; i++) {
            const float ewx = __expf(wb[cur][i].x);
            const float ewy = __expf(wb[cur][i].y);
            const float ekx = __expf(kb[cur][i].x);
            const float eky = __expf(kb[cur][i].y);
            a.x = fmaf(ewx, a.x, ekx);
            a.y = fmaf(ewy, a.y, eky);
            b.x = fmaf(ewx, b.x, ekx * vb[cur][i].x);
            b.y = fmaf(ewy, b.y, eky * vb[cur][i].y);
            if (DO_OUT) {
                float2 r;
                r.x = __fdividef(b.x, a.x);
                r.y = __fdividef(b.y, a.y);
                __stcs(o + i * DD2, r);
            } else {
                p.x *= ewx;
                p.y *= ewy;
            }
        }
        cur = nxt;
    }
    // epilogue inner block
    float2* o = op + (NB - 1) * UU * DD2;
#pragma unroll
    for (int i = 0; i < UU; i++) {
        const float ewx = __expf(wb[cur][i].x);
        const float ewy = __expf(wb[cur][i].y);
        const float ekx = __expf(kb[cur][i].x);
        const float eky = __expf(kb[cur][i].y);
        a.x = fmaf(ewx, a.x, ekx);
        a.y = fmaf(ewy, a.y, eky);
        b.x = fmaf(ewx, b.x, ekx * vb[cur][i].x);
        b.y = fmaf(ewy, b.y, eky * vb[cur][i].y);
        if (DO_OUT) {
            float2 r;
            r.x = __fdividef(b.x, a.x);
            r.y = __fdividef(b.y, a.y);
            __stcs(o + i * DD2, r);
        } else {
            p.x *= ewx;
            p.y *= ewy;
        }
    }
}

// pass1: bx<64 -> chunk0 exact; bx in [64,192) -> summaries for chunks 1,2.
__global__ void __launch_bounds__(128, 1)
wkv_pass1(const float2* __restrict__ k,
          const float2* __restrict__ v,
          const float2* __restrict__ w,
          float2* __restrict__ out)
{
    const int bx = blockIdx.x;
    float2 a = make_float2(0.f, 0.f);
    float2 b = make_float2(0.f, 0.f);
    float2 p = make_float2(1.f, 1.f);

    if (bx < 64) {
        const int ch = bx * 128 + threadIdx.x;               // pair index
        const long base = (long)(ch >> 9) * TT * DD2 + (ch & (DD2 - 1));
        run_chunk<1>(k + base, v + base, w + base, out + base, a, b, p);
        g_scr[0 * NCH2 + ch] = a;                            // state @ t=512
        g_scr[1 * NCH2 + ch] = b;
    } else {
        const int j  = 1 + ((bx - 64) >> 6);                 // chunk 1 or 2
        const int ch = ((bx - 64) & 63) * 128 + threadIdx.x;
        const long base = (long)(ch >> 9) * TT * DD2 + (ch & (DD2 - 1))
                        + (long)j * LCH * DD2;
        run_chunk<0>(k + base, v + base, w + base, (float2*)nullptr, a, b, p);
        const int s = 2 + (j - 1) * 3;
        g_scr[(s + 0) * NCH2 + ch] = p;
        g_scr[(s + 1) * NCH2 + ch] = a;
        g_scr[(s + 2) * NCH2 + ch] = b;
    }
}

// pass2: chunks 1..3 exact, carry-in composed from scratch.
__global__ void __launch_bounds__(128, 1)
wkv_pass2(const float2* __restrict__ k,
          const float2* __restrict__ v,
          const float2* __restrict__ w,
          float2* __restrict__ out)
{
    const int bx = blockIdx.x;
    const int j  = 1 + (bx >> 6);                            // chunk 1..3
    const int ch = (bx & 63) * 128 + threadIdx.x;

    float2 a = g_scr[0 * NCH2 + ch];                         // state @ t=512
    float2 b = g_scr[1 * NCH2 + ch];
    if (j >= 2) {                                            // -> t=1024
        const float2 P = g_scr[2 * NCH2 + ch];
        const float2 A = g_scr[3 * NCH2 + ch];
        const float2 Bs = g_scr[4 * NCH2 + ch];
        a.x = fmaf(P.x, a.x, A.x);  a.y = fmaf(P.y, a.y, A.y);
        b.x = fmaf(P.x, b.x, Bs.x); b.y = fmaf(P.y, b.y, Bs.y);
    }
    if (j == 3) {                                            // -> t=1536
        const float2 P = g_scr[5 * NCH2 + ch];
        const float2 A = g_scr[6 * NCH2 + ch];
        const float2 Bs = g_scr[7 * NCH2 + ch];
        a.x = fmaf(P.x, a.x, A.x);  a.y = fmaf(P.y, a.y, A.y);
        b.x = fmaf(P.x, b.x, Bs.x); b.y = fmaf(P.y, b.y, Bs.y);
    }

    const long base = (long)(ch >> 9) * TT * DD2 + (ch & (DD2 - 1))
                    + (long)j * LCH * DD2;
    float2 p = make_float2(1.f, 1.f);
    run_chunk<1>(k + base, v + base, w + base, out + base, a, b, p);
}

extern "C" void kernel_launch(void* const* d_in, const int* in_sizes, int n_in,
                              void* d_out, int out_size)
{
    const float2* k = (const float2*)d_in[0];
    const float2* v = (const float2*)d_in[1];
    const float2* w = (const float2*)d_in[2];
    float2* out = (float2*)d_out;

    wkv_pass1<<<192, 128>>>(k, v, w, out);   // chunk0 exact + summaries 1,2
    wkv_pass2<<<192, 128>>>(k, v, w, out);   // chunks 1..3 exact
}

// round 9
// speedup vs baseline: 2.2703x; 2.2703x over previous
#include <cuda_runtime.h>
#include <cstdint>

// RWKV WKV recurrence, B=16, T=2048, D=1024 fp32. Single pass (536MB, the
// traffic floor). Each WARP is a private pipeline: it owns 32 consecutive
// channels and a private 4-slot x 12KB SMEM ring filled with cp.async.cg
// (LDGSTS: un-scoreboarded, uncapped in-flight depth -> DRAM latency fully
// decoupled at 4 warps/SM). Sync is cp.async.wait_group + __syncwarp only;
// no __syncthreads anywhere (R3's per-stage block barriers were the killer).

#define TT 2048
#define DD 1024
#define SL 32                           // timesteps per stage
#define NSTAGE (TT / SL)                // 64
#define RING 4                          // slots per warp
#define SLOT_F (3 * SL * 32)            // floats per slot  = 3072 (12KB)
#define WREG_F (RING * SLOT_F)          // floats per warp region = 12288

extern __shared__ float sm[];

__device__ __forceinline__ void cpasync16(uint32_t d, const void* s) {
    asm volatile("cp.async.cg.shared.global [%0], [%1], 16;\n"
                 :: "r"(d), "l"(s) : "memory");
}
__device__ __forceinline__ void cp_commit() {
    asm volatile("cp.async.commit_group;\n" ::: "memory");
}
__device__ __forceinline__ void cp_wait3() {
    asm volatile("cp.async.wait_group 3;\n" ::: "memory");
}

__global__ void __launch_bounds__(128, 1)
wkv_kernel(const float* __restrict__ k,
           const float* __restrict__ v,
           const float* __restrict__ w,
           float* __restrict__ out)
{
    const int tid  = threadIdx.x;
    const int warp = tid >> 5;
    const int lane = tid & 31;

    const int ch0 = blockIdx.x * 128 + warp * 32;   // warp's first channel
    const int bi  = ch0 >> 10;                      // batch (32 | 1024: no crossing)
    const int d0  = ch0 & (DD - 1);
    const long gbase = (long)bi * TT * DD + d0;

    // ---- loader-side per-thread constants ----
    // Each warp-instr: 32 lanes x 16B = 4 rows x 128B of one tensor.
    const int r_off = lane >> 3;          // row within 4-row group
    const int c4    = (lane & 7) * 4;     // float offset within 32-ch slice
    const float* pk = k + gbase + (long)r_off * DD + c4;
    const float* pv = v + gbase + (long)r_off * DD + c4;
    const float* pw = w + gbase + (long)r_off * DD + c4;

    const uint32_t smu   = (uint32_t)__cvta_generic_to_shared(sm);
    const uint32_t dstb  = smu + (uint32_t)(warp * WREG_F) * 4u
                         + (uint32_t)(r_off * 32 + (lane & 7) * 4) * 4u;

    // ---- reader-side ----
    const float* srd = sm + warp * WREG_F + lane;   // column = channel
    float* go = out + gbase + lane;

    // Issue one stage into `slot`: 24 LDGSTS (3 tensors x 8 x 4-row groups),
    // all immediate-offset from 3 advancing base pointers.
    auto issue = [&](int slot) {
        const uint32_t db = dstb + (uint32_t)(slot * SLOT_F) * 4u;
#pragma unroll
        for (int it = 0; it < 8; it++)
            cpasync16(db + 0u * 4096u + (uint32_t)it * 512u, pk + (long)it * 4 * DD);
#pragma unroll
        for (int it = 0; it < 8; it++)
            cpasync16(db + 1u * 4096u + (uint32_t)it * 512u, pv + (long)it * 4 * DD);
#pragma unroll
        for (int it = 0; it < 8; it++)
            cpasync16(db + 2u * 4096u + (uint32_t)it * 512u, pw + (long)it * 4 * DD);
        cp_commit();
        pk += SL * DD; pv += SL * DD; pw += SL * DD;
    };

    // Prologue: fill the ring (4 groups in flight = 48KB/warp).
    issue(0); issue(1); issue(2); issue(3);

    float a = 0.0f, b = 0.0f;

    for (int s = 0; s < NSTAGE; s++) {
        cp_wait3();          // group s complete (<=3 pending)
        __syncwarp();        // cross-lane visibility of this warp's copies

        const float* sb = srd + (s & (RING - 1)) * SLOT_F;
#pragma unroll
        for (int i = 0; i < SL; i++) {
            const float kk = sb[i * 32];
            const float vv = sb[SL * 32 + i * 32];          // +1024
            const float ww = sb[2 * SL * 32 + i * 32];      // +2048
            const float ew = __expf(ww);
            const float ek = __expf(kk);
            a = fmaf(ew, a, ek);
            b = fmaf(ew, b, ek * vv);
            __stcs(go + (long)i * DD, __fdividef(b, a));
        }
        go += (long)SL * DD;

        __syncwarp();        // all lanes done reading slot before refill
        if (s + RING < NSTAGE) issue(s & (RING - 1));
        else                   cp_commit();   // empty group keeps invariant
    }
}

extern "C" void kernel_launch(void* const* d_in, const int* in_sizes, int n_in,
                              void* d_out, int out_size)
{
    const float* k = (const float*)d_in[0];
    const float* v = (const float*)d_in[1];
    const float* w = (const float*)d_in[2];
    float* out = (float*)d_out;

    const int smem_bytes = 4 * WREG_F * (int)sizeof(float);  // 196608
    cudaFuncSetAttribute(wkv_kernel,
                         cudaFuncAttributeMaxDynamicSharedMemorySize, smem_bytes);

    // 16384 channels / (4 warps x 32 ch) = 128 blocks, one per SM.
    wkv_kernel<<<128, 128, smem_bytes>>>(k, v, w, out);
}